// round 9
// baseline (speedup 1.0000x reference)
#include <cuda_runtime.h>

// DotProcessorBlock: feat = x*w + b (per row, N=256)
// out[b, k] = feat[k>>8] * feat[k&255] for k in [0, 32896)
// B=4096 rows, ~539 MB of pure f32 stores -> HBM-write-bound (~91% of spec).
// R9: CHUNKS=16 (proven best quantum) with 128-thread blocks so each thread
//     issues 4 stores (vs 2): prologue amortized 2x, same SM concurrency
//     (16 CTAs/SM), same per-CTA drain granularity as R7.

#define N_FEAT 256
#define NUM_OUT 32896                 // N*(N+1)/2
#define OUT_VEC4 (NUM_OUT / 4)        // 8224 float4 per row
#define CHUNKS 16
#define CHUNK_V4 (OUT_VEC4 / CHUNKS)  // 514 float4 per chunk = 4*128 + 2
#define BLOCK 128

__global__ __launch_bounds__(BLOCK, 16)
void dot_outer_kernel(const float* __restrict__ x,
                      const float* __restrict__ w,
                      const float* __restrict__ bias,
                      float* __restrict__ out)
{
    const int row   = blockIdx.x >> 4;          // / CHUNKS
    const int chunk = blockIdx.x & (CHUNKS - 1);
    const int tid   = threadIdx.x;

    const int t0 = chunk * CHUNK_V4 + tid;
    const int j  = t0 & 63;                     // float4 column; invariant under +128/+512
                                                // (128 % 64 == 0, 512 % 64 == 0)

    const float4* __restrict__ x4 = reinterpret_cast<const float4*>(x) + (size_t)row * (N_FEAT / 4);
    const float4* __restrict__ w4 = reinterpret_cast<const float4*>(w);
    const float4* __restrict__ b4 = reinterpret_cast<const float4*>(bias);

    // fj = feat[4j..4j+3] in registers (no smem, no barrier, warp-private latency)
    const float4 xa = x4[j];
    const float4 wa = w4[j];
    const float4 ba = b4[j];
    float4 fj;
    fj.x = fmaf(xa.x, wa.x, ba.x);
    fj.y = fmaf(xa.y, wa.y, ba.y);
    fj.z = fmaf(xa.z, wa.z, ba.z);
    fj.w = fmaf(xa.w, wa.w, ba.w);

    const float* __restrict__ xr = x + (size_t)row * N_FEAT;
    float4* __restrict__ out4 = reinterpret_cast<float4*>(out) + (size_t)row * OUT_VEC4;

    // 4 full iterations: fi = feat[t>>6], near-uniform per warp (<=2 values, L1-hot)
    #pragma unroll
    for (int it = 0; it < 4; ++it) {
        const int t = t0 + it * BLOCK;
        const int i = t >> 6;
        const float fi = fmaf(xr[i], w[i], bias[i]);
        float4 v;
        v.x = fj.x * fi; v.y = fj.y * fi; v.z = fj.z * fi; v.w = fj.w * fi;
        __stcs(&out4[t], v);
    }
    // 2-element tail (threads 0..1); fj index unchanged since 512 % 64 == 0
    if (tid < (CHUNK_V4 - 4 * BLOCK)) {
        const int t = t0 + 4 * BLOCK;
        const int i = t >> 6;
        const float fi = fmaf(xr[i], w[i], bias[i]);
        float4 v;
        v.x = fj.x * fi; v.y = fj.y * fi; v.z = fj.z * fi; v.w = fj.w * fi;
        __stcs(&out4[t], v);
    }
}

extern "C" void kernel_launch(void* const* d_in, const int* in_sizes, int n_in,
                              void* d_out, int out_size)
{
    const float* x    = (const float*)d_in[0];
    const float* w    = (const float*)d_in[1];
    const float* bias = (const float*)d_in[2];
    float* out        = (float*)d_out;

    const int B = in_sizes[0] / N_FEAT;   // 4096
    dot_outer_kernel<<<B * CHUNKS, BLOCK>>>(x, w, bias, out);
}

// round 10
// speedup vs baseline: 1.6044x; 1.6044x over previous
#include <cuda_runtime.h>

// DotProcessorBlock: feat = x*w + b (per row, N=256)
// out[b, k] = feat[k>>8] * feat[k&255] for k in [0, 32896)
// B=4096 rows, ~539 MB of pure f32 stores -> HBM-write-bound (~91% of spec).
// R10: R7 shape (CHUNKS=16, BLOCK=256) but with ALIGNED 512-float4 chunks:
//      every warp's 512B store covers exactly 4 cache lines (R7's 514-float4
//      chunks put odd chunks at +32B, splitting every store across 5 lines).
//      The 32-float4/row remainder is spread 2-per-chunk on threads 0..1.

#define N_FEAT 256
#define NUM_OUT 32896                 // N*(N+1)/2
#define OUT_VEC4 (NUM_OUT / 4)        // 8224 float4 per row
#define CHUNKS 16
#define CHUNK_V4 512                  // aligned main body per chunk (2 x 256)
#define REM_BASE (CHUNKS * CHUNK_V4)  // 8192; remainder = 32 float4 per row

__global__ __launch_bounds__(256, 8)
void dot_outer_kernel(const float* __restrict__ x,
                      const float* __restrict__ w,
                      const float* __restrict__ bias,
                      float* __restrict__ out)
{
    const int row   = blockIdx.x >> 4;          // / CHUNKS
    const int chunk = blockIdx.x & (CHUNKS - 1);
    const int tid   = threadIdx.x;

    const int t0 = chunk * CHUNK_V4 + tid;      // 512-aligned chunk base
    const int j  = tid & 63;                    // float4 column (chunk*512 % 64 == 0)

    const float4* __restrict__ x4 = reinterpret_cast<const float4*>(x) + (size_t)row * (N_FEAT / 4);
    const float4* __restrict__ w4 = reinterpret_cast<const float4*>(w);
    const float4* __restrict__ b4 = reinterpret_cast<const float4*>(bias);

    // fj = feat[4j..4j+3] in registers (no smem, no barrier, warp-private latency)
    const float4 xa = x4[j];
    const float4 wa = w4[j];
    const float4 ba = b4[j];
    float4 fj;
    fj.x = fmaf(xa.x, wa.x, ba.x);
    fj.y = fmaf(xa.y, wa.y, ba.y);
    fj.z = fmaf(xa.z, wa.z, ba.z);
    fj.w = fmaf(xa.w, wa.w, ba.w);

    const float* __restrict__ xr = x + (size_t)row * N_FEAT;
    float4* __restrict__ out4 = reinterpret_cast<float4*>(out) + (size_t)row * OUT_VEC4;

    // Two exact iterations, branch-free, all stores 512B-aligned per warp.
    {
        const int i = t0 >> 6;                  // fi index, near-uniform per warp
        const float fi = fmaf(xr[i], w[i], bias[i]);
        float4 v = { fj.x * fi, fj.y * fi, fj.z * fi, fj.w * fi };
        __stcs(&out4[t0], v);
    }
    {
        const int t1 = t0 + 256;
        const int i = t1 >> 6;
        const float fi = fmaf(xr[i], w[i], bias[i]);
        float4 v = { fj.x * fi, fj.y * fi, fj.z * fi, fj.w * fi };
        __stcs(&out4[t1], v);
    }
    // Remainder: 32 float4 per row at [8192, 8224), 2 per chunk (threads 0..1).
    if (tid < 2) {
        const int t2 = REM_BASE + chunk * 2 + tid;
        const int i  = t2 >> 6;
        const int j2 = t2 & 63;
        const float4 xb = x4[j2];
        const float4 wb = w4[j2];
        const float4 bb = b4[j2];
        float4 fj2;
        fj2.x = fmaf(xb.x, wb.x, bb.x);
        fj2.y = fmaf(xb.y, wb.y, bb.y);
        fj2.z = fmaf(xb.z, wb.z, bb.z);
        fj2.w = fmaf(xb.w, wb.w, bb.w);
        const float fi = fmaf(xr[i], w[i], bias[i]);
        float4 v = { fj2.x * fi, fj2.y * fi, fj2.z * fi, fj2.w * fi };
        __stcs(&out4[t2], v);
    }
}

extern "C" void kernel_launch(void* const* d_in, const int* in_sizes, int n_in,
                              void* d_out, int out_size)
{
    const float* x    = (const float*)d_in[0];
    const float* w    = (const float*)d_in[1];
    const float* bias = (const float*)d_in[2];
    float* out        = (float*)d_out;

    const int B = in_sizes[0] / N_FEAT;   // 4096
    dot_outer_kernel<<<B * CHUNKS, 256>>>(x, w, bias, out);
}